// round 14
// baseline (speedup 1.0000x reference)
#include <cuda_runtime.h>

#define B 8
#define T 1024
#define E 128
#define H 8
#define S 16
#define BH (B*H)
#define KSPLIT 8

// ---- packed f32x2 helpers (sm_103a FFMA2 path, PTX-only) ----
typedef unsigned long long ull;
__device__ __forceinline__ ull ffma2(ull a, ull b, ull c) {
    ull d; asm("fma.rn.f32x2 %0, %1, %2, %3;" : "=l"(d) : "l"(a), "l"(b), "l"(c)); return d;
}
__device__ __forceinline__ ull fmul2(ull a, ull b) {
    ull d; asm("mul.rn.f32x2 %0, %1, %2;" : "=l"(d) : "l"(a), "l"(b)); return d;
}
__device__ __forceinline__ ull fadd2(ull a, ull b) {
    ull d; asm("add.rn.f32x2 %0, %1, %2;" : "=l"(d) : "l"(a), "l"(b)); return d;
}
__device__ __forceinline__ ull pack2(float lo, float hi) {
    ull d; asm("mov.b64 %0, {%1, %2};" : "=l"(d) : "f"(lo), "f"(hi)); return d;
}
__device__ __forceinline__ void unpack2(ull a, float& lo, float& hi) {
    asm("mov.b64 {%0, %1}, %2;" : "=f"(lo), "=f"(hi) : "l"(a));
}
__device__ __forceinline__ void lds2(ull& a, ull& b, unsigned addr) {
    asm("ld.shared.v2.b64 {%0, %1}, [%2];" : "=l"(a), "=l"(b) : "r"(addr));
}
__device__ __forceinline__ float ex2(float x) {
    float y; asm("ex2.approx.f32 %0, %1;" : "=f"(y) : "f"(x)); return y;
}

// ---- scratch (device globals; no allocation allowed) ----
__device__ float g_Qc[BH*T*S];     // compacted Q, scaled by 128^-0.25 * log2(e)
__device__ float g_Kc[BH*T*S];     // compacted K, scaled by 128^-0.25
__device__ float g_Vc[BH*T*S];     // compacted V
__device__ float g_WuT[E*E];       // Wu transposed
__device__ int   g_idx[B*T];       // compacted j -> original t
__device__ int   g_rank[B*T];      // original t -> compacted j (or -1)
__device__ int   g_cnt[B];         // unmasked count per batch
// split-K partials (fixed-base softmax: plain sums)
__device__ float g_pL[KSPLIT*BH*T];
__device__ float g_pO[KSPLIT*BH*T*S];

// ------------------------------------------------------------------
// 1. Compaction (blocks 0..7) + Wu transpose (blocks 8..23), fused
// ------------------------------------------------------------------
__global__ void prep_kernel(const int* __restrict__ masks,
                            const float* __restrict__ Wu) {
    if (blockIdx.x >= B) {
        int i = (blockIdx.x - B) * 1024 + threadIdx.x;
        int r = i >> 7, c = i & 127;
        g_WuT[i] = Wu[c*E + r];
        return;
    }
    int b = blockIdx.x;
    int t = threadIdx.x;            // 1024 threads
    int v = (masks[b*T + t] != 0) ? 1 : 0;
    unsigned bal = __ballot_sync(0xffffffffu, v);
    int lane = t & 31, warp = t >> 5;
    int wprefix = __popc(bal & ((1u << lane) - 1u));
    __shared__ int wcnt[32];
    __shared__ int wbase[32];
    if (lane == 31) wcnt[warp] = wprefix + v;
    __syncthreads();
    if (t == 0) {
        int acc = 0;
        for (int w = 0; w < 32; w++) { wbase[w] = acc; acc += wcnt[w]; }
        g_cnt[b] = acc;
    }
    __syncthreads();
    int r = v ? (wbase[warp] + wprefix) : -1;
    g_rank[b*T + t] = r;
    if (v) g_idx[b*T + r] = t;
}

// ------------------------------------------------------------------
// 2. QKV projection; masked rows write out = bu directly
// ------------------------------------------------------------------
__global__ __launch_bounds__(256) void qkv_kernel(
    const float* __restrict__ x, const int* __restrict__ masks,
    const float* __restrict__ Wq, const float* __restrict__ Wk,
    const float* __restrict__ Wv, const float* __restrict__ bu,
    float* __restrict__ out)
{
    __shared__ float sW[3][S*S];
    int tid = threadIdx.x;          // 256 = S*S
    sW[0][tid] = Wq[tid];
    sW[1][tid] = Wk[tid];
    sW[2][tid] = Wv[tid];
    __syncthreads();

    int gid = blockIdx.x * 256 + tid;   // (b*T + t)*H + h
    int h  = gid & 7;
    int bt = gid >> 3;
    if (!masks[bt]) {
        const float4* bb = (const float4*)(bu + h*S);
        float4* op = (float4*)(out + bt*E + h*S);
#pragma unroll
        for (int i = 0; i < 4; i++) op[i] = bb[i];
        return;
    }
    float xr[S];
    const float4* xp = (const float4*)(x + bt*E + h*S);
#pragma unroll
    for (int i = 0; i < 4; i++) {
        float4 v = xp[i];
        xr[4*i] = v.x; xr[4*i+1] = v.y; xr[4*i+2] = v.z; xr[4*i+3] = v.w;
    }
    int r = g_rank[bt];
    int b = bt >> 10;
    int base = ((b*H + h)*T + r)*S;
    const float invs   = 0.29730177875068026f;                       // 128^-0.25
    const float invs_q = 0.29730177875068026f * 1.4426950408889634f; // * log2(e)

    float o[S];
#pragma unroll
    for (int d = 0; d < S; d++) {
        float a = 0.f;
#pragma unroll
        for (int s2 = 0; s2 < S; s2++) a = fmaf(sW[0][d*S + s2], xr[s2], a);
        o[d] = a * invs_q;
    }
    {
        float4* qp = (float4*)(g_Qc + base);
#pragma unroll
        for (int i = 0; i < 4; i++) qp[i] = make_float4(o[4*i], o[4*i+1], o[4*i+2], o[4*i+3]);
    }
#pragma unroll
    for (int d = 0; d < S; d++) {
        float a = 0.f;
#pragma unroll
        for (int s2 = 0; s2 < S; s2++) a = fmaf(sW[1][d*S + s2], xr[s2], a);
        o[d] = a * invs;
    }
    {
        float4* kp = (float4*)(g_Kc + base);
#pragma unroll
        for (int i = 0; i < 4; i++) kp[i] = make_float4(o[4*i], o[4*i+1], o[4*i+2], o[4*i+3]);
    }
#pragma unroll
    for (int d = 0; d < S; d++) {
        float a = 0.f;
#pragma unroll
        for (int s2 = 0; s2 < S; s2++) a = fmaf(sW[2][d*S + s2], xr[s2], a);
        o[d] = a;
    }
    {
        float4* vp = (float4*)(g_Vc + base);
#pragma unroll
        for (int i = 0; i < 4; i++) vp[i] = make_float4(o[4*i], o[4*i+1], o[4*i+2], o[4*i+3]);
    }
}

// ------------------------------------------------------------------
// 3. Attention, fixed-base softmax (exp2), split-K, FFMA2 + LDS.128
// ------------------------------------------------------------------
#define ATH   64
#define QPT   2
#define QBLK  (ATH*QPT)
#define KTILE 128

__global__ __launch_bounds__(ATH, 8) void attn_split_kernel() {
    __shared__ float4 sK[KTILE][5];
    __shared__ float4 sV[KTILE][5];

    int bh = blockIdx.y;
    int ks = blockIdx.z;
    int b  = bh >> 3;
    int cnt = g_cnt[b];
    if ((int)(blockIdx.x * QBLK) >= cnt) return;
    int k0 = (ks * cnt) / KSPLIT;
    int k1 = ((ks + 1) * cnt) / KSPLIT;
    int tid = threadIdx.x;

    const float* Qb = g_Qc + bh*T*S;
    const float* Kb = g_Kc + bh*T*S;
    const float* Vb = g_Vc + bh*T*S;

    unsigned skb = (unsigned)__cvta_generic_to_shared(&sK[0][0]);
    unsigned svb = (unsigned)__cvta_generic_to_shared(&sV[0][0]);

    int jj[QPT];
    ull qq[QPT][8], oo[QPT][8];
    float l[QPT];
#pragma unroll
    for (int p = 0; p < QPT; p++) {
        jj[p] = blockIdx.x*QBLK + tid + p*ATH;
        const ull* qp = (const ull*)(Qb + jj[p]*S);
#pragma unroll
        for (int i = 0; i < 8; i++) { qq[p][i] = qp[i]; oo[p][i] = 0ULL; }
        l[p] = 0.f;
    }
    bool active = jj[0] < cnt;

    for (int kt = k0; kt < k1; kt += KTILE) {
        int nk = min(KTILE, k1 - kt);
        __syncthreads();
        for (int rr = tid; rr < nk; rr += ATH) {
            const float4* kp = (const float4*)(Kb + (kt+rr)*S);
            const float4* vp = (const float4*)(Vb + (kt+rr)*S);
#pragma unroll
            for (int c = 0; c < 4; c++) { sK[rr][c] = kp[c]; sV[rr][c] = vp[c]; }
        }
        __syncthreads();
        if (active) {
            for (int kk = 0; kk < nk; kk++) {
                unsigned ka = skb + kk*80u;
                unsigned va = svb + kk*80u;
                ull kv0, kv1, kv2, kv3, kv4, kv5, kv6, kv7;
                ull vv0, vv1, vv2, vv3, vv4, vv5, vv6, vv7;
                lds2(kv0, kv1, ka);       lds2(kv2, kv3, ka + 16u);
                lds2(kv4, kv5, ka + 32u); lds2(kv6, kv7, ka + 48u);
                lds2(vv0, vv1, va);       lds2(vv2, vv3, va + 16u);
                lds2(vv4, vv5, va + 32u); lds2(vv6, vv7, va + 48u);
#pragma unroll
                for (int p = 0; p < QPT; p++) {
                    ull a0 = fmul2(qq[p][0], kv0);
                    ull a1 = fmul2(qq[p][1], kv1);
                    a0 = ffma2(qq[p][2], kv2, a0);
                    a1 = ffma2(qq[p][3], kv3, a1);
                    a0 = ffma2(qq[p][4], kv4, a0);
                    a1 = ffma2(qq[p][5], kv5, a1);
                    a0 = ffma2(qq[p][6], kv6, a0);
                    a1 = ffma2(qq[p][7], kv7, a1);
                    a0 = fadd2(a0, a1);
                    float lo, hi; unpack2(a0, lo, hi);
                    float w = ex2(lo + hi);   // Q pre-scaled by log2(e)
                    l[p] += w;
                    ull wp = pack2(w, w);
                    oo[p][0] = ffma2(wp, vv0, oo[p][0]);
                    oo[p][1] = ffma2(wp, vv1, oo[p][1]);
                    oo[p][2] = ffma2(wp, vv2, oo[p][2]);
                    oo[p][3] = ffma2(wp, vv3, oo[p][3]);
                    oo[p][4] = ffma2(wp, vv4, oo[p][4]);
                    oo[p][5] = ffma2(wp, vv5, oo[p][5]);
                    oo[p][6] = ffma2(wp, vv6, oo[p][6]);
                    oo[p][7] = ffma2(wp, vv7, oo[p][7]);
                }
            }
        }
    }

#pragma unroll
    for (int p = 0; p < QPT; p++) {
        if (jj[p] < cnt) {
            int base = (ks*BH + bh)*T + jj[p];
            g_pL[base] = l[p];
            ull* op = (ull*)(g_pO + base*S);
#pragma unroll
            for (int i = 0; i < 8; i++) op[i] = oo[p][i];
        }
    }
}

// ------------------------------------------------------------------
// 4. Fused combine + projection; 4 rows per warp.
//    Gather: 32 independent LDG.128 in flight per warp.
//    GEMM: each WuT float4 reused across 4 rows (8 FFMA2 / load).
//    Rows are warp-private -> no __syncthreads, just __syncwarp.
// ------------------------------------------------------------------
#define RPW 4                 // rows per warp
#define PRJ 32                // rows per block (8 warps)
__global__ __launch_bounds__(256) void proj_kernel(const float* __restrict__ bu,
                                                   float* __restrict__ out) {
    __shared__ float xs[PRJ][E];
    int b = blockIdx.y;
    int cnt = g_cnt[b];
    int rowbase = blockIdx.x * PRJ;
    if (rowbase >= cnt) return;
    int tid  = threadIdx.x;       // 256
    int warp = tid >> 5;
    int lane = tid & 31;

    int h   = lane >> 2;          // head for this lane's 4 floats
    int off = (lane & 3) * 4;     // float offset within head
    int bh  = b*H + h;
    int ks2 = (lane & 3) * 2;     // L-splits this lane covers
    int r0  = rowbase + warp*RPW;

    // ---- gather phase: 4 rows, all loads independent ----
#pragma unroll
    for (int r = 0; r < RPW; r++) {
        int j = r0 + r;
        if (j < cnt) {
            ull a0 = 0ULL, a1 = 0ULL;
            float Lp = g_pL[(ks2*BH + bh)*T + j] + g_pL[((ks2+1)*BH + bh)*T + j];
#pragma unroll
            for (int ks = 0; ks < KSPLIT; ks++) {
                float4 v = *(const float4*)(g_pO + ((ks*BH + bh)*T + j)*S + off);
                a0 = fadd2(a0, pack2(v.x, v.y));
                a1 = fadd2(a1, pack2(v.z, v.w));
            }
            Lp += __shfl_xor_sync(0xffffffffu, Lp, 1);
            Lp += __shfl_xor_sync(0xffffffffu, Lp, 2);
            float invL = (Lp > 0.f) ? (1.0f / Lp) : 0.f;
            ull il2 = pack2(invL, invL);
            ull* xr = (ull*)&xs[warp*RPW + r][lane*4];
            xr[0] = fmul2(a0, il2);
            xr[1] = fmul2(a1, il2);
        }
    }
    __syncwarp();                 // rows are warp-private

    // ---- GEMM phase: lane = 4 cols, w reused over 4 rows ----
    int cg = lane * 4;
    ull acc[RPW][2];
#pragma unroll
    for (int r = 0; r < RPW; r++) { acc[r][0] = 0ULL; acc[r][1] = 0ULL; }
#pragma unroll 4
    for (int i = 0; i < E; i++) {
        float4 w = *(const float4*)(g_WuT + i*E + cg);
        ull wp0 = pack2(w.x, w.y), wp1 = pack2(w.z, w.w);
#pragma unroll
        for (int r = 0; r < RPW; r++) {
            float xv = xs[warp*RPW + r][i];
            ull xp = pack2(xv, xv);
            acc[r][0] = ffma2(xp, wp0, acc[r][0]);
            acc[r][1] = ffma2(xp, wp1, acc[r][1]);
        }
    }
    float4 bb = *(const float4*)(bu + cg);
#pragma unroll
    for (int r = 0; r < RPW; r++) {
        int j = r0 + r;
        if (j < cnt) {
            int t = g_idx[b*T + j];
            float o0, o1, o2, o3;
            unpack2(acc[r][0], o0, o1);
            unpack2(acc[r][1], o2, o3);
            *(float4*)(out + (b*T + t)*E + cg) =
                make_float4(o0 + bb.x, o1 + bb.y, o2 + bb.z, o3 + bb.w);
        }
    }
}

// ------------------------------------------------------------------
extern "C" void kernel_launch(void* const* d_in, const int* in_sizes, int n_in,
                              void* d_out, int out_size) {
    const float* x     = (const float*)d_in[0];
    const int*   masks = (const int*)  d_in[1];
    const float* Wq    = (const float*)d_in[2];
    const float* Wk    = (const float*)d_in[3];
    const float* Wv    = (const float*)d_in[4];
    const float* Wu    = (const float*)d_in[5];
    const float* bu    = (const float*)d_in[6];
    float* out = (float*)d_out;

    prep_kernel<<<B + 16, 1024>>>(masks, Wu);
    qkv_kernel<<<(B*T*H)/256, 256>>>(x, masks, Wq, Wk, Wv, bu, out);
    attn_split_kernel<<<dim3(T/QBLK, BH, KSPLIT), ATH>>>();
    proj_kernel<<<dim3(T/PRJ, B), 256>>>(bu, out);
}